// round 16
// baseline (speedup 1.0000x reference)
#include <cuda_runtime.h>
#include <cuda_bf16.h>

// Problem constants
#define BB 4
#define PP 64
#define SS 8
#define YD 16
#define GD 48
#define NOUT (BB*PP*PP*SS*SS)          // 1,048,576 outputs

#define WARPS_PER_BLOCK 8

__device__ __forceinline__ float dot4(float4 v, float4 w) {
    return fmaf(v.x, w.x, fmaf(v.y, w.y, fmaf(v.z, w.z, v.w * w.w)));
}

// ---------------------------------------------------------------------------
// Single kernel, NO block barrier, NO prologue. Each warp = 32 consecutive
// outputs = one 6KB contiguous g tile.
//
// Hot loop (proven R2/R13 schedule):
//   - 2 batches x 6 coalesced LDG.128 (lane l -> float4 f = l + 32k)
//   - weight column f%12 = (l%12+8k)%12 cycles {A,B,C}: 3 register float4s
//   - per-lane partial -> smem (conflict-free STS.32)
//   - lane r sums its 12 partials via 3 conflict-free LDS.128
//
// Epilogue (all 36 streaming regs dead -> register reuse; warp-cooperative,
// coalesced — NOT the scattered per-lane version that failed in R8):
//   c1[b,j,s] for s=0..7: lane l loads float4 l of the contiguous 512B row
//   y[b,j,:,:], dots with Wy[0:16] quarter (l&3), butterfly-folds quads,
//   shfl.idx picks this lane's sj. c2 symmetric with row (b,i), Wy[16:32].
//
// __launch_bounds__(256, 7): 36-reg ceiling (R13-proven safe for this hot
// loop; epilogue peak ~20 regs).
// ---------------------------------------------------------------------------
__global__ __launch_bounds__(32 * WARPS_PER_BLOCK, 7)
void fused_kernel(const float* __restrict__ y,
                  const float* __restrict__ g,
                  const float* __restrict__ Wy,
                  const float* __restrict__ by,
                  const float* __restrict__ Wg,
                  const float* __restrict__ bg,
                  float* __restrict__ out) {
    __shared__ float part[WARPS_PER_BLOCK][12 * 32];

    const int lane = threadIdx.x & 31;
    const int wIn  = threadIdx.x >> 5;
    const int warp = blockIdx.x * WARPS_PER_BLOCK + wIn;
    const int base = warp * 32;

    // ---- per-lane weight columns: (lane%12 + {0,8,4}) % 12 ----
    const int l12 = lane % 12;
    int cB = l12 + 8; if (cB >= 12) cB -= 12;
    int cC = l12 + 4; if (cC >= 12) cC -= 12;
    const float4* wv = (const float4*)Wg;
    const float4 wA = __ldg(wv + l12);
    const float4 wB = __ldg(wv + cB);
    const float4 wC = __ldg(wv + cC);

    const float4* gs = (const float4*)(g + (size_t)base * GD);
    float* p = part[wIn];

    // ---- batch 1: k = 0..5 (6 loads in flight) ----
    float4 v0 = __ldcs(gs + lane +   0);
    float4 v1 = __ldcs(gs + lane +  32);
    float4 v2 = __ldcs(gs + lane +  64);
    float4 v3 = __ldcs(gs + lane +  96);
    float4 v4 = __ldcs(gs + lane + 128);
    float4 v5 = __ldcs(gs + lane + 160);
    p[lane +   0] = dot4(v0, wA);
    p[lane +  32] = dot4(v1, wB);
    p[lane +  64] = dot4(v2, wC);
    p[lane +  96] = dot4(v3, wA);
    p[lane + 128] = dot4(v4, wB);
    p[lane + 160] = dot4(v5, wC);

    // ---- batch 2: k = 6..11 ----
    float4 u0 = __ldcs(gs + lane + 192);
    float4 u1 = __ldcs(gs + lane + 224);
    float4 u2 = __ldcs(gs + lane + 256);
    float4 u3 = __ldcs(gs + lane + 288);
    float4 u4 = __ldcs(gs + lane + 320);
    float4 u5 = __ldcs(gs + lane + 352);
    p[lane + 192] = dot4(u0, wA);
    p[lane + 224] = dot4(u1, wB);
    p[lane + 256] = dot4(u2, wC);
    p[lane + 288] = dot4(u3, wA);
    p[lane + 320] = dot4(u4, wB);
    p[lane + 352] = dot4(u5, wC);

    __syncwarp();

    // ---- reduce: lane r owns output base+r, partials at p[12r .. 12r+11] ----
    const float4* pr = (const float4*)(p + lane * 12);   // 48B aligned
    float4 t0 = pr[0], t1 = pr[1], t2 = pr[2];
    float sum = ((t0.x + t0.y) + (t0.z + t0.w))
              + ((t1.x + t1.y) + (t1.z + t1.w))
              + ((t2.x + t2.y) + (t2.z + t2.w));

    // ---- epilogue: warp-cooperative broadcast terms (streaming regs dead) ----
    const int j   = (base >> 6)  & 63;
    const int i   = (base >> 12) & 63;
    const int b   =  base >> 18;
    const int si0 = (warp & 1) << 2;

    const int q = lane & 3;
    const float4 w1 = __ldg((const float4*)Wy + q);         // Wy[0:16] seg q
    const float4 w2 = __ldg((const float4*)(Wy + YD) + q);  // Wy[16:32] seg q
    const float4* rowj = (const float4*)(y + (size_t)((b << 6) + j) * (SS * YD));
    const float4* rowi = (const float4*)(y + (size_t)((b << 6) + i) * (SS * YD));
    float p1 = dot4(__ldg(rowj + lane), w1);                // y[b,j, l>>2, 4q..]
    float p2 = dot4(__ldg(rowi + lane), w2);
    p1 += __shfl_xor_sync(0xffffffffu, p1, 1);
    p1 += __shfl_xor_sync(0xffffffffu, p1, 2);
    p2 += __shfl_xor_sync(0xffffffffu, p2, 1);
    p2 += __shfl_xor_sync(0xffffffffu, p2, 2);
    // c1[s] / c2[s] now live in all lanes of quad s
    const float c1 = __shfl_sync(0xffffffffu, p1, (lane & 7) << 2);
    const float c2 = __shfl_sync(0xffffffffu, p2, (si0 + (lane >> 3)) << 2);

    sum += c1 + c2 + __ldg(by) + __ldg(bg);

    __stcs(out + base + lane, sum);
}

// ---------------------------------------------------------------------------
// Launch
// inputs (metadata order): y(32768), pairwise_g(50331648), Wy(32), by(1),
//                          Wg(48), bg(1)
// ---------------------------------------------------------------------------
extern "C" void kernel_launch(void* const* d_in, const int* in_sizes, int n_in,
                              void* d_out, int out_size) {
    const float* y  = (const float*)d_in[0];
    const float* g  = (const float*)d_in[1];
    const float* Wy = (const float*)d_in[2];
    const float* by = (const float*)d_in[3];
    const float* Wg = (const float*)d_in[4];
    const float* bg = (const float*)d_in[5];
    float* out = (float*)d_out;

    const int tiles  = NOUT / 32;                 // 32768 warps
    const int blocks = tiles / WARPS_PER_BLOCK;   // 4096
    fused_kernel<<<blocks, 32 * WARPS_PER_BLOCK>>>(y, g, Wy, by, Wg, bg, out);
}